// round 13
// baseline (speedup 1.0000x reference)
#include <cuda_runtime.h>
#include <cuda_fp16.h>
#include <cstdint>

// FlashMoE round 12: round-10 structure (best), with cvt(x) fused into routing,
// zero_counts fused into weff, and launch order arranged so ncu -s 5 -c 1
// captures encoder_mma (launch #6).
// Routing exact via Weff = Wg@W_enc (fp32). Single-term fp16 mma everywhere.
// tcgen05 unavailable (harness PTX target compute_103).
//
// Launch order: cvtW(1) cvtU(2) cvtV(3) weff+zero(4) routing+cvtx(5)
//               encoder(6=profiled) expert(7)

#define B_TOK 16384
#define DM    2048
#define NEXP  16
#define RR    128
#define CAP   16384

__device__ int    g_cnt[NEXP];
__device__ int    g_tok[NEXP * CAP];
__device__ float  g_wgt[NEXP * CAP];
__device__ float  g_weff[NEXP * DM];
__device__ float  g_bg[NEXP];
__device__ __half g_xf[(size_t)B_TOK * DM];
__device__ __half g_wf[(size_t)DM * DM];
__device__ __half g_ef[(size_t)B_TOK * DM];
__device__ __half g_uf[(size_t)NEXP * RR * DM];
__device__ __half g_vf[(size_t)NEXP * DM * RR];

__device__ __forceinline__ uint32_t smem_u32(const void* p) {
    uint32_t a;
    asm("{ .reg .u64 t; cvta.to.shared.u64 t, %1; cvt.u32.u64 %0, t; }"
        : "=r"(a) : "l"(p));
    return a;
}
#define CP_ASYNC16(sm, gp) \
    asm volatile("cp.async.cg.shared.global [%0], [%1], 16;" :: "r"(sm), "l"(gp))
#define CP_COMMIT() asm volatile("cp.async.commit_group;" ::: "memory")
#define CP_WAIT1()  asm volatile("cp.async.wait_group 1;" ::: "memory")
#define CP_WAIT0()  asm volatile("cp.async.wait_group 0;" ::: "memory")

__device__ __forceinline__ void ldm_x4(uint32_t* r, uint32_t addr) {
    asm volatile("ldmatrix.sync.aligned.m8n8.x4.shared.b16 {%0,%1,%2,%3}, [%4];"
                 : "=r"(r[0]), "=r"(r[1]), "=r"(r[2]), "=r"(r[3]) : "r"(addr));
}
__device__ __forceinline__ void mma_f16(float* c, const uint32_t* a, const uint32_t* b) {
    asm volatile(
        "mma.sync.aligned.m16n8k16.row.col.f32.f16.f16.f32 "
        "{%0,%1,%2,%3}, {%4,%5,%6,%7}, {%8,%9}, {%0,%1,%2,%3};"
        : "+f"(c[0]), "+f"(c[1]), "+f"(c[2]), "+f"(c[3])
        : "r"(a[0]), "r"(a[1]), "r"(a[2]), "r"(a[3]), "r"(b[0]), "r"(b[1]));
}

__global__ __launch_bounds__(256) void cvt_f16(
    const float* __restrict__ src, __half* __restrict__ dst, int n)
{
    int i = (blockIdx.x * blockDim.x + threadIdx.x) * 4;
    if (i >= n) return;
    float4 v = *(const float4*)(src + i);
    __half2* dp = (__half2*)(dst + i);
    dp[0] = __half2(__float2half(v.x), __float2half(v.y));
    dp[1] = __half2(__float2half(v.z), __float2half(v.w));
}

// Weff = Wg @ W_enc ; bg = Wg @ b  (fp32, exact); also zeroes g_cnt.
__global__ __launch_bounds__(256) void weff_kernel(
    const float* __restrict__ Wg, const float* __restrict__ Wenc,
    const float* __restrict__ b)
{
    __shared__ float wg_s[NEXP][128];
    const int tid = threadIdx.x;
    const int k = blockIdx.x * 256 + tid;

    if (blockIdx.x == 0 && tid < NEXP) g_cnt[tid] = 0;

    float acc[NEXP];
    #pragma unroll
    for (int m = 0; m < NEXP; ++m) acc[m] = 0.f;

    for (int jc = 0; jc < DM; jc += 128) {
        for (int t = tid; t < NEXP * 128; t += 256)
            wg_s[t >> 7][t & 127] = Wg[(t >> 7) * DM + jc + (t & 127)];
        __syncthreads();
        for (int j = 0; j < 128; ++j) {
            float w = Wenc[(size_t)(jc + j) * DM + k];
            #pragma unroll
            for (int m = 0; m < NEXP; ++m) acc[m] += wg_s[m][j] * w;
        }
        __syncthreads();
    }
    #pragma unroll
    for (int m = 0; m < NEXP; ++m) g_weff[m * DM + k] = acc[m];

    if (blockIdx.x == 0 && tid < NEXP) {
        float s = 0.f;
        for (int j = 0; j < DM; ++j) s += Wg[tid * DM + j] * b[j];
        g_bg[tid] = s;
    }
}

// Routing from x + Weff (exact fp32). Also emits g_xf = fp16(x) (fused cvt —
// routing streams all of x anyway).
__global__ __launch_bounds__(256) void routing_kernel(
    const float* __restrict__ x)
{
    const int warp = (blockIdx.x * blockDim.x + threadIdx.x) >> 5;
    const int lane = threadIdx.x & 31;
    const int b0 = warp * 2;
    if (b0 >= B_TOK) return;

    const float4* x0 = (const float4*)(x + (size_t)b0 * DM);
    const float4* x1 = (const float4*)(x + (size_t)(b0 + 1) * DM);
    __half2* xf0 = (__half2*)(g_xf + (size_t)b0 * DM);
    __half2* xf1 = (__half2*)(g_xf + (size_t)(b0 + 1) * DM);
    const float4* wg = (const float4*)g_weff;

    float a0[NEXP], a1[NEXP];
    #pragma unroll
    for (int m = 0; m < NEXP; ++m) { a0[m] = 0.f; a1[m] = 0.f; }

    for (int it = 0; it < DM / 128; ++it) {
        int d4 = it * 32 + lane;
        float4 v0 = x0[d4];
        float4 v1 = x1[d4];
        xf0[d4 * 2]     = __half2(__float2half(v0.x), __float2half(v0.y));
        xf0[d4 * 2 + 1] = __half2(__float2half(v0.z), __float2half(v0.w));
        xf1[d4 * 2]     = __half2(__float2half(v1.x), __float2half(v1.y));
        xf1[d4 * 2 + 1] = __half2(__float2half(v1.z), __float2half(v1.w));
        #pragma unroll
        for (int m = 0; m < NEXP; ++m) {
            float4 w = wg[m * (DM / 4) + d4];
            a0[m] += v0.x*w.x + v0.y*w.y + v0.z*w.z + v0.w*w.w;
            a1[m] += v1.x*w.x + v1.y*w.y + v1.z*w.z + v1.w*w.w;
        }
    }
    #pragma unroll
    for (int m = 0; m < NEXP; ++m) {
        #pragma unroll
        for (int off = 16; off > 0; off >>= 1) {
            a0[m] += __shfl_xor_sync(0xffffffffu, a0[m], off);
            a1[m] += __shfl_xor_sync(0xffffffffu, a1[m], off);
        }
    }
    if (lane < 2) {
        float v[NEXP];
        #pragma unroll
        for (int m = 0; m < NEXP; ++m)
            v[m] = ((lane == 0) ? a0[m] : a1[m]) + g_bg[m];
        const int b = b0 + lane;

        float best = v[0]; int bi = 0;
        #pragma unroll
        for (int m = 1; m < NEXP; ++m)
            if (v[m] > best) { best = v[m]; bi = m; }
        float best2 = -3.402823466e38f; int bi2 = 0;
        #pragma unroll
        for (int m = 0; m < NEXP; ++m)
            if (m != bi && v[m] > best2) { best2 = v[m]; bi2 = m; }

        float e2 = __expf(best2 - best);
        float denom = 1.f + e2 + 1e-12f;
        float w1 = 1.f / denom;
        float w2 = e2 / denom;
        if (w1 > 1e-12f) {
            int p = atomicAdd(&g_cnt[bi], 1);
            g_tok[bi * CAP + p] = b; g_wgt[bi * CAP + p] = w1;
        }
        if (w2 > 1e-12f) {
            int p = atomicAdd(&g_cnt[bi2], 1);
            g_tok[bi2 * CAP + p] = b; g_wgt[bi2 * CAP + p] = w2;
        }
    }
}

// ===========================================================================
// Encoder: 128x128 C-tile, BK=32 double-buffered cp.async, 8 warps (32m x 64n),
// single-term fp16. Smem rows 80B-strided -> conflict-free ldmatrix.
// ===========================================================================
#define BK        32
#define N_CHUNK   (DM / BK)        // 64
#define ROW_B     80
#define TILE_B    (128 * ROW_B)    // 10240
#define ENC_SMEM  (2 * 2 * TILE_B) // 40960

__global__ __launch_bounds__(256, 2) void encoder_mma(
    const float* __restrict__ bias, float* __restrict__ out)
{
    extern __shared__ char smc[];
    const uint32_t sbase = smem_u32(smc);
    const int tid  = threadIdx.x;
    const int wid  = tid >> 5;
    const int lane = tid & 31;
    const int rowBase = blockIdx.y * 128;
    const int colBase = blockIdx.x * 128;
    const int warp_m = (wid & 3) * 32;
    const int warp_n = (wid >> 2) * 64;

    const int ldrow = tid >> 1;
    const int ldc0  = (tid & 1) * 2;
    const uint32_t srow_off = (uint32_t)(ldrow * ROW_B + ldc0 * 16);

    const __half* ga = g_xf + (size_t)(rowBase + ldrow) * DM + ldc0 * 8;
    const __half* gb = g_wf + (size_t)(colBase + ldrow) * DM + ldc0 * 8;

    float c[2][8][4];
    #pragma unroll
    for (int mi = 0; mi < 2; ++mi)
        #pragma unroll
        for (int ni = 0; ni < 8; ++ni)
            #pragma unroll
            for (int q = 0; q < 4; ++q) c[mi][ni][q] = 0.f;

    const int a_r = lane & 15;
    const int a_k = (lane >> 4) * 8;
    const int b_r = ((lane >> 4) << 3) + (lane & 7);
    const int b_k = ((lane >> 3) & 1) * 8;

    auto issue_loads = [&](int chunk, int buf) {
        const uint32_t s0 = sbase + buf * (2 * TILE_B) + srow_off;
        const size_t gofs = (size_t)chunk * BK;
        CP_ASYNC16(s0,               ga + gofs);
        CP_ASYNC16(s0 + 16,          ga + gofs + 8);
        CP_ASYNC16(s0 + TILE_B,      gb + gofs);
        CP_ASYNC16(s0 + TILE_B + 16, gb + gofs + 8);
        CP_COMMIT();
    };

    issue_loads(0, 0);

    for (int chunk = 0; chunk < N_CHUNK; ++chunk) {
        const int buf = chunk & 1;
        if (chunk + 1 < N_CHUNK) { issue_loads(chunk + 1, buf ^ 1); CP_WAIT1(); }
        else                     { CP_WAIT0(); }
        __syncthreads();

        const uint32_t tb = sbase + buf * (2 * TILE_B);
        #pragma unroll
        for (int ks = 0; ks < 2; ++ks) {
            uint32_t af[2][4], bf[4][4];
            #pragma unroll
            for (int mi = 0; mi < 2; ++mi) {
                uint32_t ao = (uint32_t)((warp_m + mi * 16 + a_r) * ROW_B
                                         + (ks * 16 + a_k) * 2);
                ldm_x4(af[mi], tb + ao);
            }
            #pragma unroll
            for (int nb = 0; nb < 4; ++nb) {
                uint32_t bo = (uint32_t)((warp_n + nb * 16 + b_r) * ROW_B
                                         + (ks * 16 + b_k) * 2);
                ldm_x4(bf[nb], tb + TILE_B + bo);
            }
            #pragma unroll
            for (int mi = 0; mi < 2; ++mi)
                #pragma unroll
                for (int nb = 0; nb < 4; ++nb) {
                    mma_f16(c[mi][nb*2],   af[mi], &bf[nb][0]);
                    mma_f16(c[mi][nb*2+1], af[mi], &bf[nb][2]);
                }
        }
        __syncthreads();
    }

    // epilogue: + bias; store fp32 to out, fp16 to g_ef
    const int erow = rowBase + warp_m + (lane >> 2);
    const int ecol0 = colBase + warp_n + (lane & 3) * 2;
    #pragma unroll
    for (int mi = 0; mi < 2; ++mi) {
        #pragma unroll
        for (int ni = 0; ni < 8; ++ni) {
            int col = ecol0 + ni * 8;
            float b0 = bias[col], b1 = bias[col + 1];
            int r0 = erow + mi * 16;
            float v00 = c[mi][ni][0] + b0, v01 = c[mi][ni][1] + b1;
            float v10 = c[mi][ni][2] + b0, v11 = c[mi][ni][3] + b1;
            size_t o0 = (size_t)r0 * DM + col;
            size_t o1 = (size_t)(r0 + 8) * DM + col;
            *(float2*)(out + o0) = make_float2(v00, v01);
            *(float2*)(out + o1) = make_float2(v10, v11);
            *(__half2*)(g_ef + o0) = __half2(__float2half(v00), __float2half(v01));
            *(__half2*)(g_ef + o1) = __half2(__float2half(v10), __float2half(v11));
        }
    }
}

// ===========================================================================
// Expert kernel, single-term fp16 (round-10 structure, atomic epilogue).
// ===========================================================================
#define ROW2_B    272
#define S_OFF     0
#define V_OFF     34816
#define EXPF_SMEM (V_OFF + 2 * 34816)   // 104448

__global__ __launch_bounds__(256, 2) void expert_f16(
    const float* __restrict__ gamma, float* __restrict__ out)
{
    const int e = blockIdx.y;
    const int n = g_cnt[e];
    const int t0 = blockIdx.x * 128;
    if (t0 >= n) return;

    extern __shared__ char smc[];
    const uint32_t sbase = smem_u32(smc);
    __shared__ int   tok_s[128];
    __shared__ float cw_s[128];

    const int tid  = threadIdx.x;
    const int wid  = tid >> 5;
    const int lane = tid & 31;
    if (tid < 128) {
        int idx = t0 + tid;
        if (idx < n) {
            tok_s[tid] = g_tok[e * CAP + idx];
            cw_s[tid]  = g_wgt[e * CAP + idx] * gamma[e];
        } else {
            tok_s[tid] = 0;
            cw_s[tid]  = 0.f;
        }
    }
    __syncthreads();

    const int warp_m = (wid & 3) * 32;
    const int warp_n = (wid >> 2) * 64;
    const int a_r = lane & 15;
    const int a_k = (lane >> 4) * 8;
    const int b_r = ((lane >> 4) << 3) + (lane & 7);
    const int b_k = ((lane >> 3) & 1) * 8;

    // ---------------- Phase 1: up-projection (K = 2048) ----------------
    {
        const int ldrow = tid >> 1;
        const int ldc0  = (tid & 1) * 2;
        const uint32_t srow_off = (uint32_t)(ldrow * ROW_B + ldc0 * 16);
        const __half* ga = g_ef + (size_t)tok_s[ldrow] * DM + ldc0 * 8;
        const __half* gb = g_uf + (size_t)e * RR * DM + (size_t)ldrow * DM + ldc0 * 8;

        float c[2][8][4];
        #pragma unroll
        for (int mi = 0; mi < 2; ++mi)
            #pragma unroll
            for (int ni = 0; ni < 8; ++ni)
                #pragma unroll
                for (int q = 0; q < 4; ++q) c[mi][ni][q] = 0.f;

        auto issue_loads = [&](int chunk, int buf) {
            const uint32_t s0 = sbase + buf * (2 * TILE_B) + srow_off;
            const size_t gofs = (size_t)chunk * BK;
            CP_ASYNC16(s0,               ga + gofs);
            CP_ASYNC16(s0 + 16,          ga + gofs + 8);
            CP_ASYNC16(s0 + TILE_B,      gb + gofs);
            CP_ASYNC16(s0 + TILE_B + 16, gb + gofs + 8);
            CP_COMMIT();
        };

        issue_loads(0, 0);
        for (int chunk = 0; chunk < N_CHUNK; ++chunk) {
            const int buf = chunk & 1;
            if (chunk + 1 < N_CHUNK) { issue_loads(chunk + 1, buf ^ 1); CP_WAIT1(); }
            else                     { CP_WAIT0(); }
            __syncthreads();

            const uint32_t tb = sbase + buf * (2 * TILE_B);
            #pragma unroll
            for (int ks = 0; ks < 2; ++ks) {
                uint32_t af[2][4], bf[4][4];
                #pragma unroll
                for (int mi = 0; mi < 2; ++mi) {
                    uint32_t ao = (uint32_t)((warp_m + mi * 16 + a_r) * ROW_B
                                             + (ks * 16 + a_k) * 2);
                    ldm_x4(af[mi], tb + ao);
                }
                #pragma unroll
                for (int nb = 0; nb < 4; ++nb) {
                    uint32_t bo = (uint32_t)((warp_n + nb * 16 + b_r) * ROW_B
                                             + (ks * 16 + b_k) * 2);
                    ldm_x4(bf[nb], tb + TILE_B + bo);
                }
                #pragma unroll
                for (int mi = 0; mi < 2; ++mi)
                    #pragma unroll
                    for (int nb = 0; nb < 4; ++nb) {
                        mma_f16(c[mi][nb*2],   af[mi], &bf[nb][0]);
                        mma_f16(c[mi][nb*2+1], af[mi], &bf[nb][2]);
                    }
            }
            __syncthreads();
        }

        // silu * cw -> S (fp16) in smem
        const int er  = warp_m + (lane >> 2);
        const int ec0 = warp_n + (lane & 3) * 2;
        #pragma unroll
        for (int mi = 0; mi < 2; ++mi) {
            int r0 = er + mi * 16;
            int r1 = r0 + 8;
            float w0 = cw_s[r0], w1 = cw_s[r1];
            #pragma unroll
            for (int ni = 0; ni < 8; ++ni) {
                int col = ec0 + ni * 8;
                float x00 = c[mi][ni][0], x01 = c[mi][ni][1];
                float x10 = c[mi][ni][2], x11 = c[mi][ni][3];
                float v00 = x00 / (1.f + __expf(-x00)) * w0;
                float v01 = x01 / (1.f + __expf(-x01)) * w0;
                float v10 = x10 / (1.f + __expf(-x10)) * w1;
                float v11 = x11 / (1.f + __expf(-x11)) * w1;
                *(__half2*)(smc + S_OFF + r0 * ROW2_B + col * 2) =
                    __half2(__float2half(v00), __float2half(v01));
                *(__half2*)(smc + S_OFF + r1 * ROW2_B + col * 2) =
                    __half2(__float2half(v10), __float2half(v11));
            }
        }
    }
    __syncthreads();

    // ---------------- Phase 2: down-projection, 16 d-tiles (K = 128) --------
    const int vrow = tid >> 1;
    const int vc0  = (tid & 1) * 8;
    const __half* gv = g_vf + (size_t)e * DM * RR + (size_t)vrow * RR + vc0 * 8;

    auto issue_v = [&](int dt, int buf) {
        const uint32_t s0 = sbase + V_OFF + buf * 34816
                          + (uint32_t)(vrow * ROW2_B + vc0 * 16);
        const __half* g = gv + (size_t)dt * 128 * RR;
        #pragma unroll
        for (int i = 0; i < 8; ++i)
            CP_ASYNC16(s0 + i * 16, g + i * 8);
        CP_COMMIT();
    };

    issue_v(0, 0);
    for (int dt = 0; dt < 16; ++dt) {
        const int buf = dt & 1;
        if (dt + 1 < 16) { issue_v(dt + 1, buf ^ 1); CP_WAIT1(); }
        else             { CP_WAIT0(); }
        __syncthreads();

        const uint32_t vb = sbase + V_OFF + buf * 34816;
        float c[2][8][4];
        #pragma unroll
        for (int mi = 0; mi < 2; ++mi)
            #pragma unroll
            for (int ni = 0; ni < 8; ++ni)
                #pragma unroll
                for (int q = 0; q < 4; ++q) c[mi][ni][q] = 0.f;

        #pragma unroll
        for (int ks = 0; ks < 8; ++ks) {
            uint32_t af[2][4], bf[4][4];
            #pragma unroll
            for (int mi = 0; mi < 2; ++mi) {
                uint32_t ao = (uint32_t)((warp_m + mi * 16 + a_r) * ROW2_B
                                         + (ks * 16 + a_k) * 2);
                ldm_x4(af[mi], sbase + S_OFF + ao);
            }
            #pragma unroll
            for (int nb = 0; nb < 4; ++nb) {
                uint32_t bo = (uint32_t)((warp_n + nb * 16 + b_r) * ROW2_B
                                         + (ks * 16 + b_k) * 2);
                ldm_x4(bf[nb], vb + bo);
            }
            #pragma unroll
            for (int mi = 0; mi < 2; ++mi)
                #pragma unroll
                for (int nb = 0; nb < 4; ++nb) {
                    mma_f16(c[mi][nb*2],   af[mi], &bf[nb][0]);
                    mma_f16(c[mi][nb*2+1], af[mi], &bf[nb][2]);
                }
        }

        const int lr0 = warp_m + (lane >> 2);
        const int col0 = dt * 128 + warp_n + (lane & 3) * 2;
        #pragma unroll
        for (int mi = 0; mi < 2; ++mi) {
            int r0 = lr0 + mi * 16;
            int r1 = r0 + 8;
            #pragma unroll
            for (int ni = 0; ni < 8; ++ni) {
                int col = col0 + ni * 8;
                if (t0 + r0 < n) {
                    float* p = out + (size_t)tok_s[r0] * DM + col;
                    atomicAdd(p,     c[mi][ni][0]);
                    atomicAdd(p + 1, c[mi][ni][1]);
                }
                if (t0 + r1 < n) {
                    float* p = out + (size_t)tok_s[r1] * DM + col;
                    atomicAdd(p,     c[mi][ni][2]);
                    atomicAdd(p + 1, c[mi][ni][3]);
                }
            }
        }
        __syncthreads();
    }
}

extern "C" void kernel_launch(void* const* d_in, const int* in_sizes, int n_in,
                              void* d_out, int out_size)
{
    const float* x    = (const float*)d_in[0];
    const float* Wenc = (const float*)d_in[1];
    const float* benc = (const float*)d_in[2];
    const float* Wg   = (const float*)d_in[3];
    const float* U    = (const float*)d_in[4];
    const float* V    = (const float*)d_in[5];
    const float* gm   = (const float*)d_in[6];
    float* out = (float*)d_out;

    cudaFuncSetAttribute(encoder_mma,
                         cudaFuncAttributeMaxDynamicSharedMemorySize, ENC_SMEM);
    cudaFuncSetAttribute(expert_f16,
                         cudaFuncAttributeMaxDynamicSharedMemorySize, EXPF_SMEM);

    __half *wf, *uf, *vf;
    cudaGetSymbolAddress((void**)&wf, g_wf);
    cudaGetSymbolAddress((void**)&uf, g_uf);
    cudaGetSymbolAddress((void**)&vf, g_vf);

    const int nw = DM * DM, nu = NEXP * RR * DM;
    // Launch order chosen so ncu (-s 5 -c 1) captures encoder_mma (#6).
    cvt_f16<<<(nw/4 + 255)/256, 256>>>(Wenc, wf, nw);        // 1
    cvt_f16<<<(nu/4 + 255)/256, 256>>>(U, uf, nu);           // 2
    cvt_f16<<<(nu/4 + 255)/256, 256>>>(V, vf, nu);           // 3
    weff_kernel<<<DM/256, 256>>>(Wg, Wenc, benc);            // 4 (+zero counts)
    routing_kernel<<<B_TOK/16, 256>>>(x);                    // 5 (+cvt x->xf)
    encoder_mma<<<dim3(DM/128, B_TOK/128), 256, ENC_SMEM>>>(benc, out);  // 6
    expert_f16<<<dim3(CAP/128, NEXP), 256, EXPF_SMEM>>>(gm, out);        // 7
}

// round 14
// speedup vs baseline: 1.0923x; 1.0923x over previous
#include <cuda_runtime.h>
#include <cuda_fp16.h>
#include <cstdint>

// FlashMoE round 14: round-10 structure (best: 1334us) with the weff_kernel
// bottleneck fixed — ncu showed it at 695us (grid=8, latency-serial).
// Now: split-K weff_part (256 blocks) + weff_reduce + warp-reduced bg.
// Routing exact via Weff = Wg@W_enc (fp32). Single-term fp16 mma everywhere.
// tcgen05 unavailable (harness PTX target compute_103).

#define B_TOK 16384
#define DM    2048
#define NEXP  16
#define RR    128
#define CAP   16384
#define KSPLIT 32          // weff split-K factor (64 j's per block)

__device__ int    g_cnt[NEXP];
__device__ int    g_tok[NEXP * CAP];
__device__ float  g_wgt[NEXP * CAP];
__device__ float  g_weff[NEXP * DM];
__device__ float  g_wpart[KSPLIT * NEXP * DM];
__device__ float  g_bg[NEXP];
__device__ __half g_xf[(size_t)B_TOK * DM];
__device__ __half g_wf[(size_t)DM * DM];
__device__ __half g_ef[(size_t)B_TOK * DM];
__device__ __half g_uf[(size_t)NEXP * RR * DM];
__device__ __half g_vf[(size_t)NEXP * DM * RR];

__device__ __forceinline__ uint32_t smem_u32(const void* p) {
    uint32_t a;
    asm("{ .reg .u64 t; cvta.to.shared.u64 t, %1; cvt.u32.u64 %0, t; }"
        : "=r"(a) : "l"(p));
    return a;
}
#define CP_ASYNC16(sm, gp) \
    asm volatile("cp.async.cg.shared.global [%0], [%1], 16;" :: "r"(sm), "l"(gp))
#define CP_COMMIT() asm volatile("cp.async.commit_group;" ::: "memory")
#define CP_WAIT1()  asm volatile("cp.async.wait_group 1;" ::: "memory")
#define CP_WAIT0()  asm volatile("cp.async.wait_group 0;" ::: "memory")

__device__ __forceinline__ void ldm_x4(uint32_t* r, uint32_t addr) {
    asm volatile("ldmatrix.sync.aligned.m8n8.x4.shared.b16 {%0,%1,%2,%3}, [%4];"
                 : "=r"(r[0]), "=r"(r[1]), "=r"(r[2]), "=r"(r[3]) : "r"(addr));
}
__device__ __forceinline__ void mma_f16(float* c, const uint32_t* a, const uint32_t* b) {
    asm volatile(
        "mma.sync.aligned.m16n8k16.row.col.f32.f16.f16.f32 "
        "{%0,%1,%2,%3}, {%4,%5,%6,%7}, {%8,%9}, {%0,%1,%2,%3};"
        : "+f"(c[0]), "+f"(c[1]), "+f"(c[2]), "+f"(c[3])
        : "r"(a[0]), "r"(a[1]), "r"(a[2]), "r"(a[3]), "r"(b[0]), "r"(b[1]));
}

__global__ __launch_bounds__(256) void cvt_f16(
    const float* __restrict__ src, __half* __restrict__ dst, int n)
{
    int i = (blockIdx.x * blockDim.x + threadIdx.x) * 4;
    if (i >= n) return;
    float4 v = *(const float4*)(src + i);
    __half2* dp = (__half2*)(dst + i);
    dp[0] = __half2(__float2half(v.x), __float2half(v.y));
    dp[1] = __half2(__float2half(v.z), __float2half(v.w));
}

// ---- weff stage 1: partial sums over 64 j's per block. Deterministic. ----
// grid (DM/256, KSPLIT), block 256.
__global__ __launch_bounds__(256) void weff_part(
    const float* __restrict__ Wg, const float* __restrict__ Wenc)
{
    __shared__ float wg_s[NEXP][64];
    const int tid = threadIdx.x;
    const int k = blockIdx.x * 256 + tid;
    const int jc = blockIdx.y * 64;

    for (int t = tid; t < NEXP * 64; t += 256)
        wg_s[t >> 6][t & 63] = Wg[(t >> 6) * DM + jc + (t & 63)];
    __syncthreads();

    float acc[NEXP];
    #pragma unroll
    for (int m = 0; m < NEXP; ++m) acc[m] = 0.f;

    #pragma unroll 4
    for (int j = 0; j < 64; ++j) {
        float w = Wenc[(size_t)(jc + j) * DM + k];
        #pragma unroll
        for (int m = 0; m < NEXP; ++m) acc[m] += wg_s[m][j] * w;
    }
    float* dst = g_wpart + (size_t)blockIdx.y * (NEXP * DM);
    #pragma unroll
    for (int m = 0; m < NEXP; ++m) dst[m * DM + k] = acc[m];
}

// ---- weff stage 2: reduce KSPLIT partials; also zero g_cnt. ----
// grid 128, block 256: one thread per (m,k) output.
__global__ __launch_bounds__(256) void weff_reduce()
{
    const int idx = blockIdx.x * 256 + threadIdx.x;   // 0..NEXP*DM-1
    if (blockIdx.x == 0 && threadIdx.x < NEXP) g_cnt[threadIdx.x] = 0;
    float s = 0.f;
    #pragma unroll
    for (int p = 0; p < KSPLIT; ++p)
        s += g_wpart[(size_t)p * (NEXP * DM) + idx];
    g_weff[idx] = s;
}

// ---- bg = Wg @ b: warp per expert, shuffle reduce. ----
__global__ __launch_bounds__(512) void bg_kernel(
    const float* __restrict__ Wg, const float* __restrict__ b)
{
    const int wid = threadIdx.x >> 5;   // expert
    const int lane = threadIdx.x & 31;
    float s = 0.f;
    for (int j = lane; j < DM; j += 32)
        s += Wg[wid * DM + j] * b[j];
    #pragma unroll
    for (int off = 16; off > 0; off >>= 1)
        s += __shfl_xor_sync(0xffffffffu, s, off);
    if (lane == 0) g_bg[wid] = s;
}

// Routing from x + Weff (exact fp32). Top-2, 2-way softmax, scatter.
__global__ __launch_bounds__(256) void routing_kernel(
    const float* __restrict__ x)
{
    const int warp = (blockIdx.x * blockDim.x + threadIdx.x) >> 5;
    const int lane = threadIdx.x & 31;
    const int b0 = warp * 2;
    if (b0 >= B_TOK) return;

    const float4* x0 = (const float4*)(x + (size_t)b0 * DM);
    const float4* x1 = (const float4*)(x + (size_t)(b0 + 1) * DM);
    const float4* wg = (const float4*)g_weff;

    float a0[NEXP], a1[NEXP];
    #pragma unroll
    for (int m = 0; m < NEXP; ++m) { a0[m] = 0.f; a1[m] = 0.f; }

    for (int it = 0; it < DM / 128; ++it) {
        int d4 = it * 32 + lane;
        float4 v0 = x0[d4];
        float4 v1 = x1[d4];
        #pragma unroll
        for (int m = 0; m < NEXP; ++m) {
            float4 w = wg[m * (DM / 4) + d4];
            a0[m] += v0.x*w.x + v0.y*w.y + v0.z*w.z + v0.w*w.w;
            a1[m] += v1.x*w.x + v1.y*w.y + v1.z*w.z + v1.w*w.w;
        }
    }
    #pragma unroll
    for (int m = 0; m < NEXP; ++m) {
        #pragma unroll
        for (int off = 16; off > 0; off >>= 1) {
            a0[m] += __shfl_xor_sync(0xffffffffu, a0[m], off);
            a1[m] += __shfl_xor_sync(0xffffffffu, a1[m], off);
        }
    }
    if (lane < 2) {
        float v[NEXP];
        #pragma unroll
        for (int m = 0; m < NEXP; ++m)
            v[m] = ((lane == 0) ? a0[m] : a1[m]) + g_bg[m];
        const int b = b0 + lane;

        float best = v[0]; int bi = 0;
        #pragma unroll
        for (int m = 1; m < NEXP; ++m)
            if (v[m] > best) { best = v[m]; bi = m; }
        float best2 = -3.402823466e38f; int bi2 = 0;
        #pragma unroll
        for (int m = 0; m < NEXP; ++m)
            if (m != bi && v[m] > best2) { best2 = v[m]; bi2 = m; }

        float e2 = __expf(best2 - best);
        float denom = 1.f + e2 + 1e-12f;
        float w1 = 1.f / denom;
        float w2 = e2 / denom;
        if (w1 > 1e-12f) {
            int p = atomicAdd(&g_cnt[bi], 1);
            g_tok[bi * CAP + p] = b; g_wgt[bi * CAP + p] = w1;
        }
        if (w2 > 1e-12f) {
            int p = atomicAdd(&g_cnt[bi2], 1);
            g_tok[bi2 * CAP + p] = b; g_wgt[bi2 * CAP + p] = w2;
        }
    }
}

// ===========================================================================
// Encoder: 128x128 C-tile, BK=32 double-buffered cp.async, 8 warps (32m x 64n),
// single-term fp16. Smem rows 80B-strided -> conflict-free ldmatrix.
// ===========================================================================
#define BK        32
#define N_CHUNK   (DM / BK)        // 64
#define ROW_B     80
#define TILE_B    (128 * ROW_B)    // 10240
#define ENC_SMEM  (2 * 2 * TILE_B) // 40960

__global__ __launch_bounds__(256, 2) void encoder_mma(
    const float* __restrict__ bias, float* __restrict__ out)
{
    extern __shared__ char smc[];
    const uint32_t sbase = smem_u32(smc);
    const int tid  = threadIdx.x;
    const int wid  = tid >> 5;
    const int lane = tid & 31;
    const int rowBase = blockIdx.y * 128;
    const int colBase = blockIdx.x * 128;
    const int warp_m = (wid & 3) * 32;
    const int warp_n = (wid >> 2) * 64;

    const int ldrow = tid >> 1;
    const int ldc0  = (tid & 1) * 2;
    const uint32_t srow_off = (uint32_t)(ldrow * ROW_B + ldc0 * 16);

    const __half* ga = g_xf + (size_t)(rowBase + ldrow) * DM + ldc0 * 8;
    const __half* gb = g_wf + (size_t)(colBase + ldrow) * DM + ldc0 * 8;

    float c[2][8][4];
    #pragma unroll
    for (int mi = 0; mi < 2; ++mi)
        #pragma unroll
        for (int ni = 0; ni < 8; ++ni)
            #pragma unroll
            for (int q = 0; q < 4; ++q) c[mi][ni][q] = 0.f;

    const int a_r = lane & 15;
    const int a_k = (lane >> 4) * 8;
    const int b_r = ((lane >> 4) << 3) + (lane & 7);
    const int b_k = ((lane >> 3) & 1) * 8;

    auto issue_loads = [&](int chunk, int buf) {
        const uint32_t s0 = sbase + buf * (2 * TILE_B) + srow_off;
        const size_t gofs = (size_t)chunk * BK;
        CP_ASYNC16(s0,               ga + gofs);
        CP_ASYNC16(s0 + 16,          ga + gofs + 8);
        CP_ASYNC16(s0 + TILE_B,      gb + gofs);
        CP_ASYNC16(s0 + TILE_B + 16, gb + gofs + 8);
        CP_COMMIT();
    };

    issue_loads(0, 0);

    for (int chunk = 0; chunk < N_CHUNK; ++chunk) {
        const int buf = chunk & 1;
        if (chunk + 1 < N_CHUNK) { issue_loads(chunk + 1, buf ^ 1); CP_WAIT1(); }
        else                     { CP_WAIT0(); }
        __syncthreads();

        const uint32_t tb = sbase + buf * (2 * TILE_B);
        #pragma unroll
        for (int ks = 0; ks < 2; ++ks) {
            uint32_t af[2][4], bf[4][4];
            #pragma unroll
            for (int mi = 0; mi < 2; ++mi) {
                uint32_t ao = (uint32_t)((warp_m + mi * 16 + a_r) * ROW_B
                                         + (ks * 16 + a_k) * 2);
                ldm_x4(af[mi], tb + ao);
            }
            #pragma unroll
            for (int nb = 0; nb < 4; ++nb) {
                uint32_t bo = (uint32_t)((warp_n + nb * 16 + b_r) * ROW_B
                                         + (ks * 16 + b_k) * 2);
                ldm_x4(bf[nb], tb + TILE_B + bo);
            }
            #pragma unroll
            for (int mi = 0; mi < 2; ++mi)
                #pragma unroll
                for (int nb = 0; nb < 4; ++nb) {
                    mma_f16(c[mi][nb*2],   af[mi], &bf[nb][0]);
                    mma_f16(c[mi][nb*2+1], af[mi], &bf[nb][2]);
                }
        }
        __syncthreads();
    }

    // epilogue: + bias; store fp32 to out, fp16 to g_ef
    const int erow = rowBase + warp_m + (lane >> 2);
    const int ecol0 = colBase + warp_n + (lane & 3) * 2;
    #pragma unroll
    for (int mi = 0; mi < 2; ++mi) {
        #pragma unroll
        for (int ni = 0; ni < 8; ++ni) {
            int col = ecol0 + ni * 8;
            float b0 = bias[col], b1 = bias[col + 1];
            int r0 = erow + mi * 16;
            float v00 = c[mi][ni][0] + b0, v01 = c[mi][ni][1] + b1;
            float v10 = c[mi][ni][2] + b0, v11 = c[mi][ni][3] + b1;
            size_t o0 = (size_t)r0 * DM + col;
            size_t o1 = (size_t)(r0 + 8) * DM + col;
            *(float2*)(out + o0) = make_float2(v00, v01);
            *(float2*)(out + o1) = make_float2(v10, v11);
            *(__half2*)(g_ef + o0) = __half2(__float2half(v00), __float2half(v01));
            *(__half2*)(g_ef + o1) = __half2(__float2half(v10), __float2half(v11));
        }
    }
}

// ===========================================================================
// Expert kernel, single-term fp16 (round-10 structure, atomic epilogue).
// ===========================================================================
#define ROW2_B    272
#define S_OFF     0
#define V_OFF     34816
#define EXPF_SMEM (V_OFF + 2 * 34816)   // 104448

__global__ __launch_bounds__(256, 2) void expert_f16(
    const float* __restrict__ gamma, float* __restrict__ out)
{
    const int e = blockIdx.y;
    const int n = g_cnt[e];
    const int t0 = blockIdx.x * 128;
    if (t0 >= n) return;

    extern __shared__ char smc[];
    const uint32_t sbase = smem_u32(smc);
    __shared__ int   tok_s[128];
    __shared__ float cw_s[128];

    const int tid  = threadIdx.x;
    const int wid  = tid >> 5;
    const int lane = tid & 31;
    if (tid < 128) {
        int idx = t0 + tid;
        if (idx < n) {
            tok_s[tid] = g_tok[e * CAP + idx];
            cw_s[tid]  = g_wgt[e * CAP + idx] * gamma[e];
        } else {
            tok_s[tid] = 0;
            cw_s[tid]  = 0.f;
        }
    }
    __syncthreads();

    const int warp_m = (wid & 3) * 32;
    const int warp_n = (wid >> 2) * 64;
    const int a_r = lane & 15;
    const int a_k = (lane >> 4) * 8;
    const int b_r = ((lane >> 4) << 3) + (lane & 7);
    const int b_k = ((lane >> 3) & 1) * 8;

    // ---------------- Phase 1: up-projection (K = 2048) ----------------
    {
        const int ldrow = tid >> 1;
        const int ldc0  = (tid & 1) * 2;
        const uint32_t srow_off = (uint32_t)(ldrow * ROW_B + ldc0 * 16);
        const __half* ga = g_ef + (size_t)tok_s[ldrow] * DM + ldc0 * 8;
        const __half* gb = g_uf + (size_t)e * RR * DM + (size_t)ldrow * DM + ldc0 * 8;

        float c[2][8][4];
        #pragma unroll
        for (int mi = 0; mi < 2; ++mi)
            #pragma unroll
            for (int ni = 0; ni < 8; ++ni)
                #pragma unroll
                for (int q = 0; q < 4; ++q) c[mi][ni][q] = 0.f;

        auto issue_loads = [&](int chunk, int buf) {
            const uint32_t s0 = sbase + buf * (2 * TILE_B) + srow_off;
            const size_t gofs = (size_t)chunk * BK;
            CP_ASYNC16(s0,               ga + gofs);
            CP_ASYNC16(s0 + 16,          ga + gofs + 8);
            CP_ASYNC16(s0 + TILE_B,      gb + gofs);
            CP_ASYNC16(s0 + TILE_B + 16, gb + gofs + 8);
            CP_COMMIT();
        };

        issue_loads(0, 0);
        for (int chunk = 0; chunk < N_CHUNK; ++chunk) {
            const int buf = chunk & 1;
            if (chunk + 1 < N_CHUNK) { issue_loads(chunk + 1, buf ^ 1); CP_WAIT1(); }
            else                     { CP_WAIT0(); }
            __syncthreads();

            const uint32_t tb = sbase + buf * (2 * TILE_B);
            #pragma unroll
            for (int ks = 0; ks < 2; ++ks) {
                uint32_t af[2][4], bf[4][4];
                #pragma unroll
                for (int mi = 0; mi < 2; ++mi) {
                    uint32_t ao = (uint32_t)((warp_m + mi * 16 + a_r) * ROW_B
                                             + (ks * 16 + a_k) * 2);
                    ldm_x4(af[mi], tb + ao);
                }
                #pragma unroll
                for (int nb = 0; nb < 4; ++nb) {
                    uint32_t bo = (uint32_t)((warp_n + nb * 16 + b_r) * ROW_B
                                             + (ks * 16 + b_k) * 2);
                    ldm_x4(bf[nb], tb + TILE_B + bo);
                }
                #pragma unroll
                for (int mi = 0; mi < 2; ++mi)
                    #pragma unroll
                    for (int nb = 0; nb < 4; ++nb) {
                        mma_f16(c[mi][nb*2],   af[mi], &bf[nb][0]);
                        mma_f16(c[mi][nb*2+1], af[mi], &bf[nb][2]);
                    }
            }
            __syncthreads();
        }

        // silu * cw -> S (fp16) in smem
        const int er  = warp_m + (lane >> 2);
        const int ec0 = warp_n + (lane & 3) * 2;
        #pragma unroll
        for (int mi = 0; mi < 2; ++mi) {
            int r0 = er + mi * 16;
            int r1 = r0 + 8;
            float w0 = cw_s[r0], w1 = cw_s[r1];
            #pragma unroll
            for (int ni = 0; ni < 8; ++ni) {
                int col = ec0 + ni * 8;
                float x00 = c[mi][ni][0], x01 = c[mi][ni][1];
                float x10 = c[mi][ni][2], x11 = c[mi][ni][3];
                float v00 = x00 / (1.f + __expf(-x00)) * w0;
                float v01 = x01 / (1.f + __expf(-x01)) * w0;
                float v10 = x10 / (1.f + __expf(-x10)) * w1;
                float v11 = x11 / (1.f + __expf(-x11)) * w1;
                *(__half2*)(smc + S_OFF + r0 * ROW2_B + col * 2) =
                    __half2(__float2half(v00), __float2half(v01));
                *(__half2*)(smc + S_OFF + r1 * ROW2_B + col * 2) =
                    __half2(__float2half(v10), __float2half(v11));
            }
        }
    }
    __syncthreads();

    // ---------------- Phase 2: down-projection, 16 d-tiles (K = 128) --------
    const int vrow = tid >> 1;
    const int vc0  = (tid & 1) * 8;
    const __half* gv = g_vf + (size_t)e * DM * RR + (size_t)vrow * RR + vc0 * 8;

    auto issue_v = [&](int dt, int buf) {
        const uint32_t s0 = sbase + V_OFF + buf * 34816
                          + (uint32_t)(vrow * ROW2_B + vc0 * 16);
        const __half* g = gv + (size_t)dt * 128 * RR;
        #pragma unroll
        for (int i = 0; i < 8; ++i)
            CP_ASYNC16(s0 + i * 16, g + i * 8);
        CP_COMMIT();
    };

    issue_v(0, 0);
    for (int dt = 0; dt < 16; ++dt) {
        const int buf = dt & 1;
        if (dt + 1 < 16) { issue_v(dt + 1, buf ^ 1); CP_WAIT1(); }
        else             { CP_WAIT0(); }
        __syncthreads();

        const uint32_t vb = sbase + V_OFF + buf * 34816;
        float c[2][8][4];
        #pragma unroll
        for (int mi = 0; mi < 2; ++mi)
            #pragma unroll
            for (int ni = 0; ni < 8; ++ni)
                #pragma unroll
                for (int q = 0; q < 4; ++q) c[mi][ni][q] = 0.f;

        #pragma unroll
        for (int ks = 0; ks < 8; ++ks) {
            uint32_t af[2][4], bf[4][4];
            #pragma unroll
            for (int mi = 0; mi < 2; ++mi) {
                uint32_t ao = (uint32_t)((warp_m + mi * 16 + a_r) * ROW2_B
                                         + (ks * 16 + a_k) * 2);
                ldm_x4(af[mi], sbase + S_OFF + ao);
            }
            #pragma unroll
            for (int nb = 0; nb < 4; ++nb) {
                uint32_t bo = (uint32_t)((warp_n + nb * 16 + b_r) * ROW2_B
                                         + (ks * 16 + b_k) * 2);
                ldm_x4(bf[nb], vb + bo);
            }
            #pragma unroll
            for (int mi = 0; mi < 2; ++mi)
                #pragma unroll
                for (int nb = 0; nb < 4; ++nb) {
                    mma_f16(c[mi][nb*2],   af[mi], &bf[nb][0]);
                    mma_f16(c[mi][nb*2+1], af[mi], &bf[nb][2]);
                }
        }

        const int lr0 = warp_m + (lane >> 2);
        const int col0 = dt * 128 + warp_n + (lane & 3) * 2;
        #pragma unroll
        for (int mi = 0; mi < 2; ++mi) {
            int r0 = lr0 + mi * 16;
            int r1 = r0 + 8;
            #pragma unroll
            for (int ni = 0; ni < 8; ++ni) {
                int col = col0 + ni * 8;
                if (t0 + r0 < n) {
                    float* p = out + (size_t)tok_s[r0] * DM + col;
                    atomicAdd(p,     c[mi][ni][0]);
                    atomicAdd(p + 1, c[mi][ni][1]);
                }
                if (t0 + r1 < n) {
                    float* p = out + (size_t)tok_s[r1] * DM + col;
                    atomicAdd(p,     c[mi][ni][2]);
                    atomicAdd(p + 1, c[mi][ni][3]);
                }
            }
        }
        __syncthreads();
    }
}

extern "C" void kernel_launch(void* const* d_in, const int* in_sizes, int n_in,
                              void* d_out, int out_size)
{
    const float* x    = (const float*)d_in[0];
    const float* Wenc = (const float*)d_in[1];
    const float* benc = (const float*)d_in[2];
    const float* Wg   = (const float*)d_in[3];
    const float* U    = (const float*)d_in[4];
    const float* V    = (const float*)d_in[5];
    const float* gm   = (const float*)d_in[6];
    float* out = (float*)d_out;

    cudaFuncSetAttribute(encoder_mma,
                         cudaFuncAttributeMaxDynamicSharedMemorySize, ENC_SMEM);
    cudaFuncSetAttribute(expert_f16,
                         cudaFuncAttributeMaxDynamicSharedMemorySize, EXPF_SMEM);

    __half *xf, *wf, *uf, *vf;
    cudaGetSymbolAddress((void**)&xf, g_xf);
    cudaGetSymbolAddress((void**)&wf, g_wf);
    cudaGetSymbolAddress((void**)&uf, g_uf);
    cudaGetSymbolAddress((void**)&vf, g_vf);

    const int nx = B_TOK * DM, nw = DM * DM, nu = NEXP * RR * DM;
    cvt_f16<<<(nx/4 + 255)/256, 256>>>(x, xf, nx);
    cvt_f16<<<(nw/4 + 255)/256, 256>>>(Wenc, wf, nw);
    cvt_f16<<<(nu/4 + 255)/256, 256>>>(U, uf, nu);
    cvt_f16<<<(nu/4 + 255)/256, 256>>>(V, vf, nu);
    weff_part<<<dim3(DM/256, KSPLIT), 256>>>(Wg, Wenc);
    weff_reduce<<<NEXP * DM / 256, 256>>>();
    bg_kernel<<<1, 512>>>(Wg, benc);
    routing_kernel<<<B_TOK/16, 256>>>(x);
    encoder_mma<<<dim3(DM/128, B_TOK/128), 256, ENC_SMEM>>>(benc, out);
    expert_f16<<<dim3(CAP/128, NEXP), 256, EXPF_SMEM>>>(gm, out);
}